// round 1
// baseline (speedup 1.0000x reference)
#include <cuda_runtime.h>

#define BB   2
#define NN   16384
#define MM   4096
#define CF   256
#define CT   128
#define CP   64
#define CTOT 384        // CF + CT interpolated channels
#define TILE 2048       // ref points per smem tile in knn kernel
#define PTS  16         // query points per block in interp kernel

// Scratch (device globals: no allocation allowed)
__device__ int   g_idx[BB * NN * 3];
__device__ float g_w[BB * NN * 3];
__device__ float g_featT[(size_t)BB * MM * CTOT];   // [B][M][384] channel-contiguous

// ---------------------------------------------------------------------------
// Kernel 1: 3-NN search. 4 lanes cooperate per query point (interleaved
// candidate stripes), merged with shfl-bfly. Computes normalized inverse-
// distance weights and stores idx/w scratch.
// ---------------------------------------------------------------------------
__global__ __launch_bounds__(256) void knn_kernel(const float* __restrict__ coords,
                                                  const float* __restrict__ refc) {
    __shared__ float4 sref[TILE];   // {rx, ry, rz, |r|^2}  (32 KB)

    int tid = threadIdx.x;
    int b   = blockIdx.x >> 8;            // 256 blocks per batch (64 pts/block)
    int n0  = (blockIdx.x & 255) * 64;
    int pt  = n0 + (tid >> 2);
    int s   = tid & 3;                    // slice within point

    const float* cp = coords + ((size_t)(b * NN + pt)) * 3;
    float px = cp[0], py = cp[1], pz = cp[2];
    float pp = px * px + py * py + pz * pz;

    float d0 = 1e30f, d1 = 1e30f, d2 = 1e30f;
    int   i0 = 0, i1 = 0, i2 = 0;

    const float* rb = refc + (size_t)b * MM * 3;

    for (int t = 0; t < MM; t += TILE) {
        __syncthreads();
        for (int m = tid; m < TILE; m += 256) {
            const float* r = rb + (size_t)(t + m) * 3;
            float rx = r[0], ry = r[1], rz = r[2];
            sref[m] = make_float4(rx, ry, rz, rx * rx + ry * ry + rz * rz);
        }
        __syncthreads();

        #pragma unroll 4
        for (int k = 0; k < TILE / 4; k++) {
            int m = 4 * k + s;
            float4 r = sref[m];
            float dt = fmaf(r.x, px, fmaf(r.y, py, r.z * pz));
            float d  = fmaf(-2.0f, dt, r.w + pp);
            int gm = t + m;
            if (d < d2) {
                if (d < d1) {
                    d2 = d1; i2 = i1;
                    if (d < d0) { d1 = d0; i1 = i0; d0 = d; i0 = gm; }
                    else        { d1 = d;  i1 = gm; }
                } else { d2 = d; i2 = gm; }
            }
        }
    }

    // Merge the 4 slices' top-3 lists (butterfly). Lane s==0 ends with result.
    for (int delta = 1; delta <= 2; delta <<= 1) {
        float od0 = __shfl_xor_sync(0xffffffffu, d0, delta);
        float od1 = __shfl_xor_sync(0xffffffffu, d1, delta);
        float od2 = __shfl_xor_sync(0xffffffffu, d2, delta);
        int   oi0 = __shfl_xor_sync(0xffffffffu, i0, delta);
        int   oi1 = __shfl_xor_sync(0xffffffffu, i1, delta);
        int   oi2 = __shfl_xor_sync(0xffffffffu, i2, delta);
        #define INS(dv, iv)                                                        \
            if (dv < d2) {                                                         \
                if (dv < d1) {                                                     \
                    d2 = d1; i2 = i1;                                              \
                    if (dv < d0) { d1 = d0; i1 = i0; d0 = dv; i0 = iv; }           \
                    else         { d1 = dv; i1 = iv; }                             \
                } else { d2 = dv; i2 = iv; }                                       \
            }
        INS(od0, oi0); INS(od1, oi1); INS(od2, oi2);
        #undef INS
    }

    if (s == 0) {
        float w0 = 1.0f / (d0 + 1e-8f);
        float w1 = 1.0f / (d1 + 1e-8f);
        float w2 = 1.0f / (d2 + 1e-8f);
        float inv = 1.0f / (w0 + w1 + w2);
        size_t base = ((size_t)(b * NN + pt)) * 3;
        g_w[base]     = w0 * inv;
        g_w[base + 1] = w1 * inv;
        g_w[base + 2] = w2 * inv;
        g_idx[base]     = i0;
        g_idx[base + 1] = i1;
        g_idx[base + 2] = i2;
    }
}

// ---------------------------------------------------------------------------
// Kernel 2: fuse ref_features [B,256,M] + ref_t_embed [B,128,M] into a
// channel-contiguous scratch g_featT [B, M, 384] via tiled 32x32 transpose.
// ---------------------------------------------------------------------------
__global__ __launch_bounds__(256) void transpose_kernel(const float* __restrict__ rf,
                                                        const float* __restrict__ rt) {
    __shared__ float tile[32][33];
    int b     = blockIdx.z;
    int mBase = blockIdx.x * 32;
    int cBase = blockIdx.y * 32;
    int tx = threadIdx.x & 31;
    int ty = threadIdx.x >> 5;   // 8 rows

    #pragma unroll
    for (int i = 0; i < 4; i++) {
        int c = cBase + ty + i * 8;
        int m = mBase + tx;
        float v;
        if (c < CF) v = rf[((size_t)b * CF + c) * MM + m];
        else        v = rt[((size_t)b * CT + (c - CF)) * MM + m];
        tile[ty + i * 8][tx] = v;
    }
    __syncthreads();
    #pragma unroll
    for (int i = 0; i < 4; i++) {
        int m = mBase + ty + i * 8;
        int c = cBase + tx;
        g_featT[((size_t)b * MM + m) * CTOT + c] = tile[tx][ty + i * 8];
    }
}

// ---------------------------------------------------------------------------
// Kernel 3: weighted gather of 3 contiguous 384-float rows per query point,
// staged through smem so the [B,C,N] output writes are coalesced along n.
// ---------------------------------------------------------------------------
__global__ __launch_bounds__(256) void interp_kernel(float* __restrict__ out) {
    __shared__ float sacc[CTOT * 17];    // [c][nl] padded (PTS=16 -> pad 17)
    __shared__ int   sidx[PTS * 3];
    __shared__ float sw[PTS * 3];

    int tid = threadIdx.x;
    int blocksPerB = NN / PTS;           // 1024
    int b  = blockIdx.x / blocksPerB;
    int n0 = (blockIdx.x % blocksPerB) * PTS;

    if (tid < PTS * 3) {
        size_t base = ((size_t)(b * NN + n0)) * 3;
        sidx[tid] = g_idx[base + tid];
        sw[tid]   = g_w[base + tid];
    }
    __syncthreads();

    const float* ft = g_featT + (size_t)b * MM * CTOT;

    for (int j = tid; j < PTS * CTOT; j += 256) {
        int nl = j / CTOT;
        int c  = j - nl * CTOT;
        int q  = nl * 3;
        float acc = sw[q]     * ft[(size_t)sidx[q]     * CTOT + c]
                  + sw[q + 1] * ft[(size_t)sidx[q + 1] * CTOT + c]
                  + sw[q + 2] * ft[(size_t)sidx[q + 2] * CTOT + c];
        sacc[c * 17 + nl] = acc;
    }
    __syncthreads();

    float* tout = out + (size_t)BB * 320 * NN;   // t_embed block after features
    for (int j = tid; j < PTS * CTOT; j += 256) {
        int c  = j >> 4;       // / PTS
        int nl = j & 15;
        float v = sacc[c * 17 + nl];
        if (c < CF) out[((size_t)b * 320 + c) * NN + n0 + nl] = v;
        else        tout[((size_t)b * CT + (c - CF)) * NN + n0 + nl] = v;
    }
}

// ---------------------------------------------------------------------------
extern "C" void kernel_launch(void* const* d_in, const int* in_sizes, int n_in,
                              void* d_out, int out_size) {
    const float* coords = (const float*)d_in[0];   // [B, N, 3]
    const float* refc   = (const float*)d_in[1];   // [B, M, 3]
    const float* rf     = (const float*)d_in[2];   // [B, 256, M]
    const float* rt     = (const float*)d_in[3];   // [B, 128, M]
    const float* pf     = (const float*)d_in[4];   // [B, 64, N]
    float* out = (float*)d_out;

    knn_kernel<<<BB * NN / 64, 256>>>(coords, refc);

    dim3 tg(MM / 32, CTOT / 32, BB);
    transpose_kernel<<<tg, 256>>>(rf, rt);

    interp_kernel<<<BB * NN / PTS, 256>>>(out);

    // Skip-feature concat: channels 256..319 of the features block are a
    // contiguous copy of points_features per batch.
    for (int b = 0; b < BB; b++) {
        cudaMemcpyAsync(out + ((size_t)b * 320 + 256) * NN,
                        pf + (size_t)b * CP * NN,
                        (size_t)CP * NN * sizeof(float),
                        cudaMemcpyDeviceToDevice);
    }
}